// round 14
// baseline (speedup 1.0000x reference)
#include <cuda_runtime.h>
#include <cuda_fp16.h>
#include <cstdint>

#define DIM 128
#define LOGN 13
#define THREADS 256
#define SCALE 0.17677669529663688f   // 32^-0.5

// ---- logits kernel smem (total 39936 B -> 4 blocks/SM) ----
// Xh : 128 rows x 64 half2, XOR-swizzled (conflict-free at every stage)
// SS : 7 stages x 256 half2 partials
#define SMO_XH 0
#define SMO_SS 32768
#define SMEM_TOTAL 39936

// packed fp16 M B-fragments, layout [s][kk][e][c] (uint2 each), read via LDG:
// uint2 at (s*8+kk)*512 + e*4 + c holds halves d = 16kk + {2c,2c+1, 2c+8,2c+9}, col e.
__device__ __align__(16) __half g_Mh[LOGN * 8 * DIM * 4 * 4];
// pair weights: [2048 tiles][7 stages][64 pairs]
__device__ __align__(16) float g_w0[2048 * 7 * 64];

// ============================ helpers ============================
__device__ __forceinline__ uint32_t h2u(__half2 h) {
    return *reinterpret_cast<uint32_t*>(&h);
}
__device__ __forceinline__ void mma_f16(float* cd,
                                        uint32_t a0, uint32_t a1, uint32_t a2, uint32_t a3,
                                        uint32_t b0, uint32_t b1) {
    asm volatile("mma.sync.aligned.m16n8k16.row.col.f32.f16.f16.f32 "
                 "{%0,%1,%2,%3}, {%4,%5,%6,%7}, {%8,%9}, {%0,%1,%2,%3};"
                 : "+f"(cd[0]), "+f"(cd[1]), "+f"(cd[2]), "+f"(cd[3])
                 : "r"(a0), "r"(a1), "r"(a2), "r"(a3), "r"(b0), "r"(b1));
}
// insert a 0 bit at position ls (a-row index -> actual row)
__device__ __forceinline__ int insert0(int i, int ls) {
    return ((i >> ls) << (ls + 1)) | (i & ((1 << ls) - 1));
}
// swizzle: f(r) = (r&7) ^ (7 if bit3(r) else 0); injective on all warp row-sets
__device__ __forceinline__ int xswz(int r) {
    return ((r ^ (((r >> 3) & 1) * 7)) & 7) << 2;
}
// half2-unit offset of (row r, half2-col e2) in the Xh tile
__device__ __forceinline__ int xoff(int r, int e2) {
    return r * 64 + (e2 ^ xswz(r));
}
// mode 0: rows = blk*128 + rr                               (stages 0..6)
// mode 1: rows = batch*8192 + t0 + 64*(rr>>6) + 128*(rr&63) (stages 7..12)
__device__ __forceinline__ int grow_of(int mode, int blk, int rr) {
    if (mode == 0) return blk * 128 + rr;
    int batch = blk >> 6, t0 = blk & 63;
    return batch * 8192 + t0 + ((rr >> 6) << 6) + ((rr & 63) << 7);
}

// ============================ precompute M ([kk][e][c] frag layout) ============================
// M[d][e] = SCALE * sum_t Wq[d][t] * Wk[e][t]
__global__ void precompute_M_kernel(const float* __restrict__ w) {
    extern __shared__ float sm[];
    float* wkT  = sm;                 // [128][129] Wk transposed (padded)
    float* wq16 = sm + DIM * 129;     // 16 rows of Wq

    const int s    = blockIdx.x;
    const int dblk = blockIdx.y * 16;
    const float* Wq = w + (size_t)(2 * s) * DIM * DIM;
    const float* Wk = Wq + DIM * DIM;

    for (int i = threadIdx.x; i < DIM * DIM; i += 512) {
        int e = i >> 7, t = i & 127;
        wkT[t * 129 + e] = Wk[i];
    }
    for (int i = threadIdx.x; i < 16 * DIM; i += 512)
        wq16[i] = Wq[(size_t)dblk * DIM + i];
    __syncthreads();

    const int e  = threadIdx.x & 127;
    const int dd = threadIdx.x >> 7;          // 0..3, each handles 4 rows
    #pragma unroll
    for (int k = 0; k < 4; k++) {
        int rl = dd * 4 + k;
        float acc = 0.0f;
        #pragma unroll 8
        for (int t = 0; t < DIM; t++)
            acc += wq16[rl * DIM + t] * wkT[t * 129 + e];
        int d  = dblk + rl;
        int kk = d >> 4, c = (d >> 1) & 3, hi = (d >> 3) & 1, lo = d & 1;
        g_Mh[(size_t)s * 16384 +
             ((((kk * 128 + e) * 4 + c) << 2) + (hi << 1) + lo)] =
            __float2half(acc * SCALE);
    }
}

// ============================ logits kernel ============================
// grid 2048: blk<1024 -> mode0 tile (stages 0..6); else mode1 (stages 7..12)
__global__ __launch_bounds__(THREADS, 4)
void logits_kernel(const float* __restrict__ x) {
    extern __shared__ char smem[];
    const uint32_t* Xh32 = (const uint32_t*)(smem + SMO_XH);
    const __half2*  Xh2  = (const __half2*)(smem + SMO_XH);
    __half2* SSp = (__half2*)(smem + SMO_SS);      // [7][256]

    const int tid  = threadIdx.x;
    const int lane = tid & 31;
    const int wid  = tid >> 5;
    const int gblk = blockIdx.x;
    const int mode = gblk >> 10;
    const int blk  = gblk & 1023;
    const int nstages   = mode ? 6 : 7;
    const int stage_off = mode ? 7 : 0;
    const int mg   = wid >> 2;        // 0..1 : 32 a-rows
    const int nq   = wid & 3;         // 0..3 : 32 e-cols
    const int g    = lane >> 2;
    const int c    = lane & 3;

    // ---- x tile -> fp16 swizzled smem ----
    for (int rr = wid; rr < 128; rr += 8) {
        int gr = grow_of(mode, blk, rr);
        float4 val = ((const float4*)x)[(size_t)gr * 32 + lane];
        uint2 pk;
        pk.x = h2u(__floats2half2_rn(val.x, val.y));
        pk.y = h2u(__floats2half2_rn(val.z, val.w));
        *(uint2*)((uint32_t*)(smem + SMO_XH) + xoff(rr, lane * 2)) = pk;
    }
    __syncthreads();

    // per-warp B base in global (L2/L1-hot: 32KB/stage shared by whole grid)
    const uint2* Mg = (const uint2*)g_Mh + (size_t)stage_off * 4096 + nq * 128 + lane;

    // ---- all stages' MMA + dots (no block barriers) ----
    #pragma unroll 1
    for (int ls = 0; ls < nstages; ls++) {
        const int i0 = mg * 32 + g, i1 = i0 + 8, i2 = i0 + 16, i3 = i0 + 24;
        const int r0 = insert0(i0, ls), r1 = insert0(i1, ls);
        const int r2 = insert0(i2, ls), r3 = insert0(i3, ls);
        const int b0r = r0 * 64, s0 = xswz(r0);
        const int b1r = r1 * 64, s1 = xswz(r1);
        const int b2r = r2 * 64, s2 = xswz(r2);
        const int b3r = r3 * 64, s3 = xswz(r3);

        float acc[2][4][4];
        #pragma unroll
        for (int t = 0; t < 2; t++)
            #pragma unroll
            for (int nt = 0; nt < 4; nt++)
                #pragma unroll
                for (int q = 0; q < 4; q++) acc[t][nt][q] = 0.0f;

        const uint2* Ms = Mg + (size_t)ls * 4096;
        #pragma unroll
        for (int kk = 0; kk < 8; kk++) {
            const uint2* bp = Ms + kk * 512;
            uint2 b0 = __ldg(bp);
            uint2 b1 = __ldg(bp + 32);
            uint2 b2 = __ldg(bp + 64);
            uint2 b3 = __ldg(bp + 96);
            const int ia = kk * 8 + c;
            uint32_t a00 = Xh32[b0r + (ia ^ s0)], a01 = Xh32[b1r + (ia ^ s1)];
            uint32_t a02 = Xh32[b0r + ((ia + 4) ^ s0)], a03 = Xh32[b1r + ((ia + 4) ^ s1)];
            uint32_t a10 = Xh32[b2r + (ia ^ s2)], a11 = Xh32[b3r + (ia ^ s3)];
            uint32_t a12 = Xh32[b2r + ((ia + 4) ^ s2)], a13 = Xh32[b3r + ((ia + 4) ^ s3)];
            mma_f16(acc[0][0], a00, a01, a02, a03, b0.x, b0.y);
            mma_f16(acc[1][0], a10, a11, a12, a13, b0.x, b0.y);
            mma_f16(acc[0][1], a00, a01, a02, a03, b1.x, b1.y);
            mma_f16(acc[1][1], a10, a11, a12, a13, b1.x, b1.y);
            mma_f16(acc[0][2], a00, a01, a02, a03, b2.x, b2.y);
            mma_f16(acc[1][2], a10, a11, a12, a13, b2.x, b2.y);
            mma_f16(acc[0][3], a00, a01, a02, a03, b3.x, b3.y);
            mma_f16(acc[1][3], a10, a11, a12, a13, b3.x, b3.y);
        }

        // dots: ss = y.xa, sc = y.xb
        {
            const int p0 = r0 | (1 << ls), p1 = r1 | (1 << ls);
            const int p2 = r2 | (1 << ls), p3 = r3 | (1 << ls);
            const int q0 = p0 * 64, t0 = xswz(p0);
            const int q1 = p1 * 64, t1 = xswz(p1);
            const int q2 = p2 * 64, t2 = xswz(p2);
            const int q3 = p3 * 64, t3 = xswz(p3);
            float ss0 = 0.f, ss1 = 0.f, ss2 = 0.f, ss3 = 0.f;
            float sc0 = 0.f, sc1 = 0.f, sc2 = 0.f, sc3 = 0.f;
            #pragma unroll
            for (int nt = 0; nt < 4; nt++) {
                const int e2 = nq * 16 + nt * 4 + c;
                float2 A0 = __half22float2(Xh2[b0r + (e2 ^ s0)]);
                float2 B0 = __half22float2(Xh2[q0 + (e2 ^ t0)]);
                float2 A1 = __half22float2(Xh2[b1r + (e2 ^ s1)]);
                float2 B1 = __half22float2(Xh2[q1 + (e2 ^ t1)]);
                float2 A2 = __half22float2(Xh2[b2r + (e2 ^ s2)]);
                float2 B2 = __half22float2(Xh2[q2 + (e2 ^ t2)]);
                float2 A3 = __half22float2(Xh2[b3r + (e2 ^ s3)]);
                float2 B3 = __half22float2(Xh2[q3 + (e2 ^ t3)]);
                ss0 += acc[0][nt][0] * A0.x + acc[0][nt][1] * A0.y;
                sc0 += acc[0][nt][0] * B0.x + acc[0][nt][1] * B0.y;
                ss1 += acc[0][nt][2] * A1.x + acc[0][nt][3] * A1.y;
                sc1 += acc[0][nt][2] * B1.x + acc[0][nt][3] * B1.y;
                ss2 += acc[1][nt][0] * A2.x + acc[1][nt][1] * A2.y;
                sc2 += acc[1][nt][0] * B2.x + acc[1][nt][1] * B2.y;
                ss3 += acc[1][nt][2] * A3.x + acc[1][nt][3] * A3.y;
                sc3 += acc[1][nt][2] * B3.x + acc[1][nt][3] * B3.y;
            }
            #pragma unroll
            for (int off = 1; off <= 2; off <<= 1) {
                ss0 += __shfl_xor_sync(0xffffffffu, ss0, off);
                sc0 += __shfl_xor_sync(0xffffffffu, sc0, off);
                ss1 += __shfl_xor_sync(0xffffffffu, ss1, off);
                sc1 += __shfl_xor_sync(0xffffffffu, sc1, off);
                ss2 += __shfl_xor_sync(0xffffffffu, ss2, off);
                sc2 += __shfl_xor_sync(0xffffffffu, sc2, off);
                ss3 += __shfl_xor_sync(0xffffffffu, ss3, off);
                sc3 += __shfl_xor_sync(0xffffffffu, sc3, off);
            }
            if (c == 0) {
                __half2* S = SSp + ls * 256 + nq * 64;
                S[i0] = __floats2half2_rn(ss0, sc0);
                S[i1] = __floats2half2_rn(ss1, sc1);
                S[i2] = __floats2half2_rn(ss2, sc2);
                S[i3] = __floats2half2_rn(ss3, sc3);
            }
        }
    }
    __syncthreads();     // all SS partials visible

    // ---- all pair weights -> global ----
    #pragma unroll
    for (int r = 0; r < 2; r++) {
        int j = tid + 256 * r;
        if (j < 64 * nstages) {
            int s = j >> 6, i = j & 63;
            const __half2* S = SSp + s * 256;
            float2 p0 = __half22float2(S[i]);
            float2 p1 = __half22float2(S[64 + i]);
            float2 p2 = __half22float2(S[128 + i]);
            float2 p3 = __half22float2(S[192 + i]);
            float s1 = p0.x + p1.x + p2.x + p3.x;
            float s2 = p0.y + p1.y + p2.y + p3.y;
            g_w0[(size_t)gblk * 448 + j] = 1.0f / (1.0f + __expf(s2 - s1));
        }
    }
}

// ============================ mix kernel (pure streaming) ============================
__global__ __launch_bounds__(THREADS)
void mix_kernel(const float* __restrict__ vsrc, float* __restrict__ out,
                int nstages, int w0_tile_off, int mode) {
    __shared__ float w0f[448];
    const int tid  = threadIdx.x;
    const int lane = tid & 31;
    const int wid  = tid >> 5;
    const int blk  = blockIdx.x;

    for (int j = tid; j < 64 * nstages; j += THREADS)
        w0f[j] = g_w0[(size_t)(w0_tile_off + blk) * 448 + j];
    __syncthreads();

    int gr4[4];
    #pragma unroll
    for (int j = 0; j < 4; j++) gr4[j] = grow_of(mode, blk, lane + 32 * j);

    #pragma unroll 1
    for (int h = 0; h < 2; h++) {
        float4 v[4][2];
        #pragma unroll
        for (int j = 0; j < 4; j++)
            #pragma unroll
            for (int k = 0; k < 2; k++)
                v[j][k] = ((const float4*)vsrc)[(size_t)gr4[j] * 32 + wid * 4 + h * 2 + k];

        for (int ls = 0; ls < nstages; ls++) {
            const int srr = 1 << ls;
            float w0v[4], w1v[4];
            #pragma unroll
            for (int j = 0; j < 4; j++) {
                int row = lane + 32 * j;
                int idx = ((row >> (ls + 1)) << ls) | (row & (srr - 1));
                w0v[j] = w0f[ls * 64 + idx];
                w1v[j] = 1.0f - w0v[j];
            }
            if (srr <= 16) {
                #pragma unroll
                for (int j = 0; j < 4; j++)
                    #pragma unroll
                    for (int k = 0; k < 2; k++) {
                        float4 val = v[j][k];
                        float4 pv;
                        pv.x = __shfl_xor_sync(0xffffffffu, val.x, srr);
                        pv.y = __shfl_xor_sync(0xffffffffu, val.y, srr);
                        pv.z = __shfl_xor_sync(0xffffffffu, val.z, srr);
                        pv.w = __shfl_xor_sync(0xffffffffu, val.w, srr);
                        v[j][k].x = w0v[j] * val.x + w1v[j] * pv.x;
                        v[j][k].y = w0v[j] * val.y + w1v[j] * pv.y;
                        v[j][k].z = w0v[j] * val.z + w1v[j] * pv.z;
                        v[j][k].w = w0v[j] * val.w + w1v[j] * pv.w;
                    }
            } else {
                const int dj = srr >> 5;     // 1 (stride 32) or 2 (stride 64)
                #pragma unroll
                for (int k = 0; k < 2; k++) {
                    const float4 ps[4] = {v[0][k], v[1][k], v[2][k], v[3][k]};
                    #pragma unroll
                    for (int j = 0; j < 4; j++) {
                        float4 a = ps[j], b = ps[j ^ dj];
                        v[j][k].x = w0v[j] * a.x + w1v[j] * b.x;
                        v[j][k].y = w0v[j] * a.y + w1v[j] * b.y;
                        v[j][k].z = w0v[j] * a.z + w1v[j] * b.z;
                        v[j][k].w = w0v[j] * a.w + w1v[j] * b.w;
                    }
                }
            }
        }

        #pragma unroll
        for (int j = 0; j < 4; j++)
            #pragma unroll
            for (int k = 0; k < 2; k++)
                ((float4*)out)[(size_t)gr4[j] * 32 + wid * 4 + h * 2 + k] = v[j][k];
    }
}

// ============================ launch ============================
extern "C" void kernel_launch(void* const* d_in, const int* in_sizes, int n_in,
                              void* d_out, int out_size) {
    const float* x = (const float*)d_in[0];   // (16, 8192, 128) f32
    const float* w = (const float*)d_in[1];   // (16, 2, 128, 128) f32
    float* out = (float*)d_out;

    const int smem_pre = (DIM * 129 + 16 * DIM) * 4;
    cudaFuncSetAttribute(precompute_M_kernel,
                         cudaFuncAttributeMaxDynamicSharedMemorySize, smem_pre);
    cudaFuncSetAttribute(logits_kernel,
                         cudaFuncAttributeMaxDynamicSharedMemorySize, SMEM_TOTAL);

    precompute_M_kernel<<<dim3(LOGN, 8), 512, smem_pre>>>(w);
    // all 13 stages' pair weights, 2048 independent tiles
    logits_kernel<<<2048, THREADS, SMEM_TOTAL>>>(x);
    // v mixing: stages 0..6 then 7..12 (pure streaming)
    mix_kernel<<<1024, THREADS>>>(x, out, 7, 0, 0);
    mix_kernel<<<1024, THREADS>>>(out, out, 6, 1024, 1);
}

// round 15
// speedup vs baseline: 1.2410x; 1.2410x over previous
#include <cuda_runtime.h>
#include <cuda_fp16.h>
#include <cstdint>

#define DIM 128
#define LOGN 13
#define THREADS 256
#define SCALE 0.17677669529663688f   // 32^-0.5

// ---- dynamic smem byte offsets (total 39936 B -> 4 blocks/SM w/ bounds) ----
// Xh : 128 rows x 64 half2, XOR-swizzled (conflict-free at every stage)
//      (reused in Phase C as 128 x 16 float4 swizzled v-transpose buffer)
// SS : 7 stages x 256 half2 partials (aliased by w0f f32[448] in phase B/C)
#define SMO_XH 0
#define SMO_SS 32768
#define SMEM_TOTAL 39936

// packed fp16 M B-fragments, layout [s][kk][e][c] (uint2 each), read via LDG:
// uint2 at (s*8+kk)*512 + e*4 + c holds halves d = 16kk + {2c,2c+1, 2c+8,2c+9}, col e.
__device__ __align__(16) __half g_Mh[LOGN * 8 * DIM * 4 * 4];

// ============================ helpers ============================
__device__ __forceinline__ uint32_t h2u(__half2 h) {
    return *reinterpret_cast<uint32_t*>(&h);
}
__device__ __forceinline__ void mma_f16(float* cd,
                                        uint32_t a0, uint32_t a1, uint32_t a2, uint32_t a3,
                                        uint32_t b0, uint32_t b1) {
    asm volatile("mma.sync.aligned.m16n8k16.row.col.f32.f16.f16.f32 "
                 "{%0,%1,%2,%3}, {%4,%5,%6,%7}, {%8,%9}, {%0,%1,%2,%3};"
                 : "+f"(cd[0]), "+f"(cd[1]), "+f"(cd[2]), "+f"(cd[3])
                 : "r"(a0), "r"(a1), "r"(a2), "r"(a3), "r"(b0), "r"(b1));
}
// insert a 0 bit at position ls (a-row index -> actual row)
__device__ __forceinline__ int insert0(int i, int ls) {
    return ((i >> ls) << (ls + 1)) | (i & ((1 << ls) - 1));
}
// swizzle: f(r) = (r&7) ^ (7 if bit3(r) else 0); injective on all warp row-sets
__device__ __forceinline__ int xswz(int r) {
    return ((r ^ (((r >> 3) & 1) * 7)) & 7) << 2;
}
// half2-unit offset of (row r, half2-col e2) in the Xh tile
__device__ __forceinline__ int xoff(int r, int e2) {
    return r * 64 + (e2 ^ xswz(r));
}
// Phase-C v transpose buffer: float4 index of (row r, float4-col f), swizzled
__device__ __forceinline__ int scf(int r, int f) {
    return r * 16 + (f ^ ((r >> 1) & 7));
}

// ============================ precompute M ([kk][e][c] frag layout) ============================
// M[d][e] = SCALE * sum_t Wq[d][t] * Wk[e][t]
__global__ void precompute_M_kernel(const float* __restrict__ w) {
    extern __shared__ float sm[];
    float* wkT  = sm;                 // [128][129] Wk transposed (padded)
    float* wq16 = sm + DIM * 129;     // 16 rows of Wq

    const int s    = blockIdx.x;
    const int dblk = blockIdx.y * 16;
    const float* Wq = w + (size_t)(2 * s) * DIM * DIM;
    const float* Wk = Wq + DIM * DIM;

    for (int i = threadIdx.x; i < DIM * DIM; i += 512) {
        int e = i >> 7, t = i & 127;
        wkT[t * 129 + e] = Wk[i];
    }
    for (int i = threadIdx.x; i < 16 * DIM; i += 512)
        wq16[i] = Wq[(size_t)dblk * DIM + i];
    __syncthreads();

    const int e  = threadIdx.x & 127;
    const int dd = threadIdx.x >> 7;          // 0..3, each handles 4 rows
    #pragma unroll
    for (int k = 0; k < 4; k++) {
        int rl = dd * 4 + k;
        float acc = 0.0f;
        #pragma unroll 8
        for (int t = 0; t < DIM; t++)
            acc += wq16[rl * DIM + t] * wkT[t * 129 + e];
        int d  = dblk + rl;
        int kk = d >> 4, c = (d >> 1) & 3, hi = (d >> 3) & 1, lo = d & 1;
        g_Mh[(size_t)s * 16384 +
             ((((kk * 128 + e) * 4 + c) << 2) + (hi << 1) + lo)] =
            __float2half(acc * SCALE);
    }
}

// ============================ fused butterfly ============================
// mode 0: rows = blk*128 + rr                               (stages 0..6)
// mode 1: rows = batch*8192 + t0 + 64*(rr>>6) + 128*(rr&63) (stages 7..12)
__device__ __forceinline__ int grow_of(int mode, int blk, int rr) {
    if (mode == 0) return blk * 128 + rr;
    int batch = blk >> 6, t0 = blk & 63;
    return batch * 8192 + t0 + ((rr >> 6) << 6) + ((rr & 63) << 7);
}

__global__ __launch_bounds__(THREADS, 4)
void butterfly_kernel(const float* __restrict__ x, float* __restrict__ out,
                      int nstages, int stage_off, int mode) {
    extern __shared__ char smem[];
    const uint32_t* Xh32 = (const uint32_t*)(smem + SMO_XH);
    const __half2*  Xh2  = (const __half2*)(smem + SMO_XH);
    __half2* SSp = (__half2*)(smem + SMO_SS);      // [7][256]
    float*   w0f = (float*)(smem + SMO_SS);        // alias, valid after phase B

    const int tid  = threadIdx.x;
    const int lane = tid & 31;
    const int wid  = tid >> 5;
    const int blk  = blockIdx.x;
    const int mg   = wid >> 2;        // 0..1 : 32 a-rows
    const int nq   = wid & 3;         // 0..3 : 32 e-cols
    const int g    = lane >> 2;
    const int c    = lane & 3;

    // ---- x tile -> fp16 swizzled smem (one 8B STS per row per lane) ----
    for (int rr = wid; rr < 128; rr += 8) {
        int gr = grow_of(mode, blk, rr);
        float4 val = ((const float4*)x)[(size_t)gr * 32 + lane];
        uint2 pk;
        pk.x = h2u(__floats2half2_rn(val.x, val.y));
        pk.y = h2u(__floats2half2_rn(val.z, val.w));
        *(uint2*)((uint32_t*)(smem + SMO_XH) + xoff(rr, lane * 2)) = pk;
    }
    __syncthreads();

    // per-warp B base in global (L2/L1-hot: 32KB/stage shared by whole grid)
    const uint2* Mg = (const uint2*)g_Mh + (size_t)stage_off * 4096 + nq * 128 + lane;

    // ================= Phase A: all stages' MMA + dots (NO block barriers) ===
    #pragma unroll 1
    for (int ls = 0; ls < nstages; ls++) {
        // a-rows of this thread
        const int i0 = mg * 32 + g, i1 = i0 + 8, i2 = i0 + 16, i3 = i0 + 24;
        const int r0 = insert0(i0, ls), r1 = insert0(i1, ls);
        const int r2 = insert0(i2, ls), r3 = insert0(i3, ls);
        const int b0r = r0 * 64, s0 = xswz(r0);
        const int b1r = r1 * 64, s1 = xswz(r1);
        const int b2r = r2 * 64, s2 = xswz(r2);
        const int b3r = r3 * 64, s3 = xswz(r3);

        // ---- MMA: Y = X_a * M  (8 k16 steps, fp16 in / fp32 acc) ----
        float acc[2][4][4];
        #pragma unroll
        for (int t = 0; t < 2; t++)
            #pragma unroll
            for (int nt = 0; nt < 4; nt++)
                #pragma unroll
                for (int q = 0; q < 4; q++) acc[t][nt][q] = 0.0f;

        const uint2* Ms = Mg + (size_t)ls * 4096;
        #pragma unroll
        for (int kk = 0; kk < 8; kk++) {
            // B loads first (independent -> MLP), then A LDS, then MMAs
            const uint2* bp = Ms + kk * 512;
            uint2 b0 = __ldg(bp);
            uint2 b1 = __ldg(bp + 32);
            uint2 b2 = __ldg(bp + 64);
            uint2 b3 = __ldg(bp + 96);
            const int ia = kk * 8 + c;
            uint32_t a00 = Xh32[b0r + (ia ^ s0)], a01 = Xh32[b1r + (ia ^ s1)];
            uint32_t a02 = Xh32[b0r + ((ia + 4) ^ s0)], a03 = Xh32[b1r + ((ia + 4) ^ s1)];
            uint32_t a10 = Xh32[b2r + (ia ^ s2)], a11 = Xh32[b3r + (ia ^ s3)];
            uint32_t a12 = Xh32[b2r + ((ia + 4) ^ s2)], a13 = Xh32[b3r + ((ia + 4) ^ s3)];
            mma_f16(acc[0][0], a00, a01, a02, a03, b0.x, b0.y);
            mma_f16(acc[1][0], a10, a11, a12, a13, b0.x, b0.y);
            mma_f16(acc[0][1], a00, a01, a02, a03, b1.x, b1.y);
            mma_f16(acc[1][1], a10, a11, a12, a13, b1.x, b1.y);
            mma_f16(acc[0][2], a00, a01, a02, a03, b2.x, b2.y);
            mma_f16(acc[1][2], a10, a11, a12, a13, b2.x, b2.y);
            mma_f16(acc[0][3], a00, a01, a02, a03, b3.x, b3.y);
            mma_f16(acc[1][3], a10, a11, a12, a13, b3.x, b3.y);
        }

        // ---- dots: ss = y.xa, sc = y.xb  (fp16 x reads, conflict-free) ----
        {
            const int p0 = r0 | (1 << ls), p1 = r1 | (1 << ls);
            const int p2 = r2 | (1 << ls), p3 = r3 | (1 << ls);
            const int q0 = p0 * 64, t0 = xswz(p0);
            const int q1 = p1 * 64, t1 = xswz(p1);
            const int q2 = p2 * 64, t2 = xswz(p2);
            const int q3 = p3 * 64, t3 = xswz(p3);
            float ss0 = 0.f, ss1 = 0.f, ss2 = 0.f, ss3 = 0.f;
            float sc0 = 0.f, sc1 = 0.f, sc2 = 0.f, sc3 = 0.f;
            #pragma unroll
            for (int nt = 0; nt < 4; nt++) {
                const int e2 = nq * 16 + nt * 4 + c;      // half2 col index
                float2 A0 = __half22float2(Xh2[b0r + (e2 ^ s0)]);
                float2 B0 = __half22float2(Xh2[q0 + (e2 ^ t0)]);
                float2 A1 = __half22float2(Xh2[b1r + (e2 ^ s1)]);
                float2 B1 = __half22float2(Xh2[q1 + (e2 ^ t1)]);
                float2 A2 = __half22float2(Xh2[b2r + (e2 ^ s2)]);
                float2 B2 = __half22float2(Xh2[q2 + (e2 ^ t2)]);
                float2 A3 = __half22float2(Xh2[b3r + (e2 ^ s3)]);
                float2 B3 = __half22float2(Xh2[q3 + (e2 ^ t3)]);
                ss0 += acc[0][nt][0] * A0.x + acc[0][nt][1] * A0.y;
                sc0 += acc[0][nt][0] * B0.x + acc[0][nt][1] * B0.y;
                ss1 += acc[0][nt][2] * A1.x + acc[0][nt][3] * A1.y;
                sc1 += acc[0][nt][2] * B1.x + acc[0][nt][3] * B1.y;
                ss2 += acc[1][nt][0] * A2.x + acc[1][nt][1] * A2.y;
                sc2 += acc[1][nt][0] * B2.x + acc[1][nt][1] * B2.y;
                ss3 += acc[1][nt][2] * A3.x + acc[1][nt][3] * A3.y;
                sc3 += acc[1][nt][2] * B3.x + acc[1][nt][3] * B3.y;
            }
            #pragma unroll
            for (int off = 1; off <= 2; off <<= 1) {
                ss0 += __shfl_xor_sync(0xffffffffu, ss0, off);
                sc0 += __shfl_xor_sync(0xffffffffu, sc0, off);
                ss1 += __shfl_xor_sync(0xffffffffu, ss1, off);
                sc1 += __shfl_xor_sync(0xffffffffu, sc1, off);
                ss2 += __shfl_xor_sync(0xffffffffu, ss2, off);
                sc2 += __shfl_xor_sync(0xffffffffu, sc2, off);
                ss3 += __shfl_xor_sync(0xffffffffu, ss3, off);
                sc3 += __shfl_xor_sync(0xffffffffu, sc3, off);
            }
            if (c == 0) {
                __half2* S = SSp + ls * 256 + nq * 64;
                S[i0] = __floats2half2_rn(ss0, sc0);
                S[i1] = __floats2half2_rn(ss1, sc1);
                S[i2] = __floats2half2_rn(ss2, sc2);
                S[i3] = __floats2half2_rn(ss3, sc3);
            }
        }
    }
    __syncthreads();     // all SS partials visible

    // ================= Phase B: all pair weights (w0f aliases SS) ============
    {
        float w0sv[2];
        #pragma unroll
        for (int r = 0; r < 2; r++) {
            int j = tid + 256 * r;
            w0sv[r] = 0.0f;
            if (j < 64 * nstages) {
                int s = j >> 6, i = j & 63;
                const __half2* S = SSp + s * 256;
                float2 p0 = __half22float2(S[i]);
                float2 p1 = __half22float2(S[64 + i]);
                float2 p2 = __half22float2(S[128 + i]);
                float2 p3 = __half22float2(S[192 + i]);
                float s1 = p0.x + p1.x + p2.x + p3.x;
                float s2 = p0.y + p1.y + p2.y + p3.y;
                w0sv[r] = 1.0f / (1.0f + __expf(s2 - s1));
            }
        }
        __syncthreads();     // all SS reads done before aliased writes
        #pragma unroll
        for (int r = 0; r < 2; r++) {
            int j = tid + 256 * r;
            if (j < 64 * nstages) w0f[j] = w0sv[r];
        }
    }
    __syncthreads();

    // ================= Phase C: v mixes, smem-staged coalesced I/O ===========
    float4* scr4 = (float4*)smem;            // Xh region is dead: 128 x 16 f4
    const float4* vsrc = (mode == 0) ? (const float4*)x : (const float4*)out;
    const int rw0 = wid * 2 + (lane >> 4);   // fill/drain row base
    const int fc  = lane & 15;               // fill/drain float4 col

    #pragma unroll 1
    for (int h = 0; h < 2; h++) {
        // coalesced global load -> swizzled smem (warp = 2 rows x 256B)
        #pragma unroll
        for (int rr = rw0; rr < 128; rr += 16) {
            int gr = grow_of(mode, blk, rr);
            scr4[scf(rr, fc)] = vsrc[(size_t)gr * 32 + h * 16 + fc];
        }
        __syncthreads();

        // transpose gather: thread owns rows lane+32j, f4-cols wid*2+k
        float4 v[4][2];
        #pragma unroll
        for (int j = 0; j < 4; j++)
            #pragma unroll
            for (int k = 0; k < 2; k++)
                v[j][k] = scr4[scf(lane + 32 * j, wid * 2 + k)];

        for (int ls = 0; ls < nstages; ls++) {
            const int srr = 1 << ls;
            float w0v[4], w1v[4];
            #pragma unroll
            for (int j = 0; j < 4; j++) {
                int row = lane + 32 * j;
                int idx = ((row >> (ls + 1)) << ls) | (row & (srr - 1));
                w0v[j] = w0f[ls * 64 + idx];
                w1v[j] = 1.0f - w0v[j];
            }
            if (srr <= 16) {
                #pragma unroll
                for (int j = 0; j < 4; j++)
                    #pragma unroll
                    for (int k = 0; k < 2; k++) {
                        float4 val = v[j][k];
                        float4 pv;
                        pv.x = __shfl_xor_sync(0xffffffffu, val.x, srr);
                        pv.y = __shfl_xor_sync(0xffffffffu, val.y, srr);
                        pv.z = __shfl_xor_sync(0xffffffffu, val.z, srr);
                        pv.w = __shfl_xor_sync(0xffffffffu, val.w, srr);
                        v[j][k].x = w0v[j] * val.x + w1v[j] * pv.x;
                        v[j][k].y = w0v[j] * val.y + w1v[j] * pv.y;
                        v[j][k].z = w0v[j] * val.z + w1v[j] * pv.z;
                        v[j][k].w = w0v[j] * val.w + w1v[j] * pv.w;
                    }
            } else {
                const int dj = srr >> 5;     // 1 (stride 32) or 2 (stride 64)
                #pragma unroll
                for (int k = 0; k < 2; k++) {
                    const float4 ps[4] = {v[0][k], v[1][k], v[2][k], v[3][k]};
                    #pragma unroll
                    for (int j = 0; j < 4; j++) {
                        float4 a = ps[j], b = ps[j ^ dj];
                        v[j][k].x = w0v[j] * a.x + w1v[j] * b.x;
                        v[j][k].y = w0v[j] * a.y + w1v[j] * b.y;
                        v[j][k].z = w0v[j] * a.z + w1v[j] * b.z;
                        v[j][k].w = w0v[j] * a.w + w1v[j] * b.w;
                    }
                }
            }
        }

        // transpose scatter back (each element touched by exactly one thread)
        #pragma unroll
        for (int j = 0; j < 4; j++)
            #pragma unroll
            for (int k = 0; k < 2; k++)
                scr4[scf(lane + 32 * j, wid * 2 + k)] = v[j][k];
        __syncthreads();

        // coalesced global store
        #pragma unroll
        for (int rr = rw0; rr < 128; rr += 16) {
            int gr = grow_of(mode, blk, rr);
            ((float4*)out)[(size_t)gr * 32 + h * 16 + fc] = scr4[scf(rr, fc)];
        }
        __syncthreads();     // scr reused next half
    }
}

// ============================ launch ============================
extern "C" void kernel_launch(void* const* d_in, const int* in_sizes, int n_in,
                              void* d_out, int out_size) {
    const float* x = (const float*)d_in[0];   // (16, 8192, 128) f32
    const float* w = (const float*)d_in[1];   // (16, 2, 128, 128) f32
    float* out = (float*)d_out;

    const int smem_pre = (DIM * 129 + 16 * DIM) * 4;
    cudaFuncSetAttribute(precompute_M_kernel,
                         cudaFuncAttributeMaxDynamicSharedMemorySize, smem_pre);
    cudaFuncSetAttribute(butterfly_kernel,
                         cudaFuncAttributeMaxDynamicSharedMemorySize, SMEM_TOTAL);

    precompute_M_kernel<<<dim3(LOGN, 8), 512, smem_pre>>>(w);
    // stages 0..6 (strides 1..64): 128 contiguous rows per block
    butterfly_kernel<<<1024, THREADS, SMEM_TOTAL>>>(x, out, 7, 0, 0);
    // stages 7..12 (strides 128..4096): rows t0 + 64h + 128j per block
    butterfly_kernel<<<1024, THREADS, SMEM_TOTAL>>>(x, out, 6, 7, 1);
}

// round 16
// speedup vs baseline: 1.2766x; 1.0287x over previous
#include <cuda_runtime.h>
#include <cuda_fp16.h>
#include <cstdint>

#define DIM 128
#define LOGN 13
#define THREADS 256
#define SCALE 0.17677669529663688f   // 32^-0.5

// ---- dynamic smem byte offsets (total 39936 B -> 4 blocks/SM w/ bounds) ----
// Xh : 128 rows x 64 half2, XOR-swizzled (conflict-free at every stage)
//      (reused in Phase C as 128 x 16 float4 swizzled v-transpose buffer)
// SS : 7 stages x 256 half2 partials (aliased by w0f f32[448] in phase B/C)
#define SMO_XH 0
#define SMO_SS 32768
#define SMEM_TOTAL 39936

// packed fp16 M B-fragments, layout [s][kk][e][c] (uint2 each), read via LDG:
// uint2 at (s*8+kk)*512 + e*4 + c holds halves d = 16kk + {2c,2c+1, 2c+8,2c+9}, col e.
__device__ __align__(16) __half g_Mh[LOGN * 8 * DIM * 4 * 4];

// ============================ helpers ============================
__device__ __forceinline__ uint32_t h2u(__half2 h) {
    return *reinterpret_cast<uint32_t*>(&h);
}
__device__ __forceinline__ void mma_f16(float* cd,
                                        uint32_t a0, uint32_t a1, uint32_t a2, uint32_t a3,
                                        uint32_t b0, uint32_t b1) {
    asm volatile("mma.sync.aligned.m16n8k16.row.col.f32.f16.f16.f32 "
                 "{%0,%1,%2,%3}, {%4,%5,%6,%7}, {%8,%9}, {%0,%1,%2,%3};"
                 : "+f"(cd[0]), "+f"(cd[1]), "+f"(cd[2]), "+f"(cd[3])
                 : "r"(a0), "r"(a1), "r"(a2), "r"(a3), "r"(b0), "r"(b1));
}
// insert a 0 bit at position ls (a-row index -> actual row)
__device__ __forceinline__ int insert0(int i, int ls) {
    return ((i >> ls) << (ls + 1)) | (i & ((1 << ls) - 1));
}
// swizzle: f(r) = (r&7) ^ (7 if bit3(r) else 0); injective on all warp row-sets
__device__ __forceinline__ int xswz(int r) {
    return ((r ^ (((r >> 3) & 1) * 7)) & 7) << 2;
}
// half2-unit offset of (row r, half2-col e2) in the Xh tile
__device__ __forceinline__ int xoff(int r, int e2) {
    return r * 64 + (e2 ^ xswz(r));
}
// Phase-C v transpose buffer: float4 index of (row r, float4-col f), swizzled
__device__ __forceinline__ int scf(int r, int f) {
    return r * 16 + (f ^ ((r >> 1) & 7));
}

// ============================ precompute M ([kk][e][c] frag layout) ============================
// M[d][e] = SCALE * sum_t Wq[d][t] * Wk[e][t]; grid (13, 32), 1 e-row/thread
__global__ void precompute_M_kernel(const float* __restrict__ w) {
    extern __shared__ float sm[];
    float* wqT = sm;                  // [128][129] Wq transposed (padded)
    float* wk4 = sm + DIM * 129;      // 4 rows of Wk

    const int s    = blockIdx.x;
    const int eblk = blockIdx.y * 4;
    const float* Wq = w + (size_t)(2 * s) * DIM * DIM;
    const float* Wk = Wq + DIM * DIM;

    for (int i = threadIdx.x; i < DIM * DIM; i += 512) {
        int d = i >> 7, t = i & 127;
        wqT[t * 129 + d] = Wq[i];
    }
    for (int i = threadIdx.x; i < 4 * DIM; i += 512)
        wk4[i] = Wk[(size_t)eblk * DIM + i];
    __syncthreads();

    const int d  = threadIdx.x & 127;
    const int el = threadIdx.x >> 7;          // 0..3, one e-row each
    float acc = 0.0f;
    #pragma unroll 8
    for (int t = 0; t < DIM; t++)
        acc += wk4[el * DIM + t] * wqT[t * 129 + d];
    const int e = eblk + el;
    const int kk = d >> 4, c = (d >> 1) & 3, hi = (d >> 3) & 1, lo = d & 1;
    g_Mh[(size_t)s * 16384 +
         ((((kk * 128 + e) * 4 + c) << 2) + (hi << 1) + lo)] =
        __float2half(acc * SCALE);
}

// ============================ fused butterfly ============================
// mode 0: rows = blk*128 + rr                               (stages 0..6)
// mode 1: rows = batch*8192 + t0 + 64*(rr>>6) + 128*(rr&63) (stages 7..12)
__device__ __forceinline__ int grow_of(int mode, int blk, int rr) {
    if (mode == 0) return blk * 128 + rr;
    int batch = blk >> 6, t0 = blk & 63;
    return batch * 8192 + t0 + ((rr >> 6) << 6) + ((rr & 63) << 7);
}

__global__ __launch_bounds__(THREADS, 4)
void butterfly_kernel(const float* __restrict__ x, float* __restrict__ out,
                      int nstages, int stage_off, int mode) {
    extern __shared__ char smem[];
    const uint32_t* Xh32 = (const uint32_t*)(smem + SMO_XH);
    const __half2*  Xh2  = (const __half2*)(smem + SMO_XH);
    __half2* SSp = (__half2*)(smem + SMO_SS);      // [7][256]
    float*   w0f = (float*)(smem + SMO_SS);        // alias, valid after phase B

    const int tid  = threadIdx.x;
    const int lane = tid & 31;
    const int wid  = tid >> 5;
    const int blk  = blockIdx.x;
    const int mg   = wid >> 2;        // 0..1 : 32 a-rows
    const int nq   = wid & 3;         // 0..3 : 32 e-cols
    const int g    = lane >> 2;
    const int c    = lane & 3;

    // ---- x tile -> fp16 swizzled smem (one 8B STS per row per lane) ----
    for (int rr = wid; rr < 128; rr += 8) {
        int gr = grow_of(mode, blk, rr);
        float4 val = ((const float4*)x)[(size_t)gr * 32 + lane];
        uint2 pk;
        pk.x = h2u(__floats2half2_rn(val.x, val.y));
        pk.y = h2u(__floats2half2_rn(val.z, val.w));
        *(uint2*)((uint32_t*)(smem + SMO_XH) + xoff(rr, lane * 2)) = pk;
    }
    __syncthreads();

    // per-warp B base in global (L2/L1-hot: 32KB/stage shared by whole grid)
    const uint2* Mg = (const uint2*)g_Mh + (size_t)stage_off * 4096 + nq * 128 + lane;

    // ================= Phase A: all stages' MMA + dots (NO block barriers) ===
    #pragma unroll 1
    for (int ls = 0; ls < nstages; ls++) {
        // a-rows of this thread
        const int i0 = mg * 32 + g, i1 = i0 + 8, i2 = i0 + 16, i3 = i0 + 24;
        const int r0 = insert0(i0, ls), r1 = insert0(i1, ls);
        const int r2 = insert0(i2, ls), r3 = insert0(i3, ls);
        const int b0r = r0 * 64, s0 = xswz(r0);
        const int b1r = r1 * 64, s1 = xswz(r1);
        const int b2r = r2 * 64, s2 = xswz(r2);
        const int b3r = r3 * 64, s3 = xswz(r3);

        // ---- MMA: Y = X_a * M  (8 k16 steps, fp16 in / fp32 acc) ----
        float acc[2][4][4];
        #pragma unroll
        for (int t = 0; t < 2; t++)
            #pragma unroll
            for (int nt = 0; nt < 4; nt++)
                #pragma unroll
                for (int q = 0; q < 4; q++) acc[t][nt][q] = 0.0f;

        const uint2* Ms = Mg + (size_t)ls * 4096;
        #pragma unroll
        for (int kk = 0; kk < 8; kk++) {
            // B loads first (independent -> MLP), then A LDS, then MMAs
            const uint2* bp = Ms + kk * 512;
            uint2 b0 = __ldg(bp);
            uint2 b1 = __ldg(bp + 32);
            uint2 b2 = __ldg(bp + 64);
            uint2 b3 = __ldg(bp + 96);
            const int ia = kk * 8 + c;
            uint32_t a00 = Xh32[b0r + (ia ^ s0)], a01 = Xh32[b1r + (ia ^ s1)];
            uint32_t a02 = Xh32[b0r + ((ia + 4) ^ s0)], a03 = Xh32[b1r + ((ia + 4) ^ s1)];
            uint32_t a10 = Xh32[b2r + (ia ^ s2)], a11 = Xh32[b3r + (ia ^ s3)];
            uint32_t a12 = Xh32[b2r + ((ia + 4) ^ s2)], a13 = Xh32[b3r + ((ia + 4) ^ s3)];
            mma_f16(acc[0][0], a00, a01, a02, a03, b0.x, b0.y);
            mma_f16(acc[1][0], a10, a11, a12, a13, b0.x, b0.y);
            mma_f16(acc[0][1], a00, a01, a02, a03, b1.x, b1.y);
            mma_f16(acc[1][1], a10, a11, a12, a13, b1.x, b1.y);
            mma_f16(acc[0][2], a00, a01, a02, a03, b2.x, b2.y);
            mma_f16(acc[1][2], a10, a11, a12, a13, b2.x, b2.y);
            mma_f16(acc[0][3], a00, a01, a02, a03, b3.x, b3.y);
            mma_f16(acc[1][3], a10, a11, a12, a13, b3.x, b3.y);
        }

        // ---- dots: ss = y.xa, sc = y.xb  (fp16 HFMA2, 4-deep chains) ----
        {
            const int p0 = r0 | (1 << ls), p1 = r1 | (1 << ls);
            const int p2 = r2 | (1 << ls), p3 = r3 | (1 << ls);
            const int q0 = p0 * 64, t0 = xswz(p0);
            const int q1 = p1 * 64, t1 = xswz(p1);
            const int q2 = p2 * 64, t2 = xswz(p2);
            const int q3 = p3 * 64, t3 = xswz(p3);
            const __half2 hz = __floats2half2_rn(0.f, 0.f);
            __half2 sh0 = hz, sh1 = hz, sh2 = hz, sh3 = hz;
            __half2 ch0 = hz, ch1 = hz, ch2 = hz, ch3 = hz;
            #pragma unroll
            for (int nt = 0; nt < 4; nt++) {
                const int e2 = nq * 16 + nt * 4 + c;      // half2 col index
                __half2 y0 = __floats2half2_rn(acc[0][nt][0], acc[0][nt][1]);
                __half2 y1 = __floats2half2_rn(acc[0][nt][2], acc[0][nt][3]);
                __half2 y2 = __floats2half2_rn(acc[1][nt][0], acc[1][nt][1]);
                __half2 y3 = __floats2half2_rn(acc[1][nt][2], acc[1][nt][3]);
                sh0 = __hfma2(y0, Xh2[b0r + (e2 ^ s0)], sh0);
                ch0 = __hfma2(y0, Xh2[q0 + (e2 ^ t0)], ch0);
                sh1 = __hfma2(y1, Xh2[b1r + (e2 ^ s1)], sh1);
                ch1 = __hfma2(y1, Xh2[q1 + (e2 ^ t1)], ch1);
                sh2 = __hfma2(y2, Xh2[b2r + (e2 ^ s2)], sh2);
                ch2 = __hfma2(y2, Xh2[q2 + (e2 ^ t2)], ch2);
                sh3 = __hfma2(y3, Xh2[b3r + (e2 ^ s3)], sh3);
                ch3 = __hfma2(y3, Xh2[q3 + (e2 ^ t3)], ch3);
            }
            float2 f;
            f = __half22float2(sh0); float ss0 = f.x + f.y;
            f = __half22float2(ch0); float sc0 = f.x + f.y;
            f = __half22float2(sh1); float ss1 = f.x + f.y;
            f = __half22float2(ch1); float sc1 = f.x + f.y;
            f = __half22float2(sh2); float ss2 = f.x + f.y;
            f = __half22float2(ch2); float sc2 = f.x + f.y;
            f = __half22float2(sh3); float ss3 = f.x + f.y;
            f = __half22float2(ch3); float sc3 = f.x + f.y;
            #pragma unroll
            for (int off = 1; off <= 2; off <<= 1) {
                ss0 += __shfl_xor_sync(0xffffffffu, ss0, off);
                sc0 += __shfl_xor_sync(0xffffffffu, sc0, off);
                ss1 += __shfl_xor_sync(0xffffffffu, ss1, off);
                sc1 += __shfl_xor_sync(0xffffffffu, sc1, off);
                ss2 += __shfl_xor_sync(0xffffffffu, ss2, off);
                sc2 += __shfl_xor_sync(0xffffffffu, sc2, off);
                ss3 += __shfl_xor_sync(0xffffffffu, ss3, off);
                sc3 += __shfl_xor_sync(0xffffffffu, sc3, off);
            }
            if (c == 0) {
                __half2* S = SSp + ls * 256 + nq * 64;
                S[i0] = __floats2half2_rn(ss0, sc0);
                S[i1] = __floats2half2_rn(ss1, sc1);
                S[i2] = __floats2half2_rn(ss2, sc2);
                S[i3] = __floats2half2_rn(ss3, sc3);
            }
        }
    }
    __syncthreads();     // all SS partials visible

    // ================= Phase B: all pair weights (w0f aliases SS) ============
    {
        float w0sv[2];
        #pragma unroll
        for (int r = 0; r < 2; r++) {
            int j = tid + 256 * r;
            w0sv[r] = 0.0f;
            if (j < 64 * nstages) {
                int s = j >> 6, i = j & 63;
                const __half2* S = SSp + s * 256;
                float2 p0 = __half22float2(S[i]);
                float2 p1 = __half22float2(S[64 + i]);
                float2 p2 = __half22float2(S[128 + i]);
                float2 p3 = __half22float2(S[192 + i]);
                float s1 = p0.x + p1.x + p2.x + p3.x;
                float s2 = p0.y + p1.y + p2.y + p3.y;
                w0sv[r] = 1.0f / (1.0f + __expf(s2 - s1));
            }
        }
        __syncthreads();     // all SS reads done before aliased writes
        #pragma unroll
        for (int r = 0; r < 2; r++) {
            int j = tid + 256 * r;
            if (j < 64 * nstages) w0f[j] = w0sv[r];
        }
    }
    __syncthreads();

    // ================= Phase C: v mixes, smem-staged coalesced I/O ===========
    float4* scr4 = (float4*)smem;            // Xh region is dead: 128 x 16 f4
    const float4* vsrc = (mode == 0) ? (const float4*)x : (const float4*)out;
    const int rw0 = wid * 2 + (lane >> 4);   // fill/drain row base
    const int fc  = lane & 15;               // fill/drain float4 col

    #pragma unroll 1
    for (int h = 0; h < 2; h++) {
        // coalesced global load -> swizzled smem (warp = 2 rows x 256B)
        #pragma unroll
        for (int rr = rw0; rr < 128; rr += 16) {
            int gr = grow_of(mode, blk, rr);
            scr4[scf(rr, fc)] = vsrc[(size_t)gr * 32 + h * 16 + fc];
        }
        __syncthreads();

        // transpose gather: thread owns rows lane+32j, f4-cols wid*2+k
        float4 v[4][2];
        #pragma unroll
        for (int j = 0; j < 4; j++)
            #pragma unroll
            for (int k = 0; k < 2; k++)
                v[j][k] = scr4[scf(lane + 32 * j, wid * 2 + k)];

        for (int ls = 0; ls < nstages; ls++) {
            const int srr = 1 << ls;
            float w0v[4], w1v[4];
            #pragma unroll
            for (int j = 0; j < 4; j++) {
                int row = lane + 32 * j;
                int idx = ((row >> (ls + 1)) << ls) | (row & (srr - 1));
                w0v[j] = w0f[ls * 64 + idx];
                w1v[j] = 1.0f - w0v[j];
            }
            if (srr <= 16) {
                #pragma unroll
                for (int j = 0; j < 4; j++)
                    #pragma unroll
                    for (int k = 0; k < 2; k++) {
                        float4 val = v[j][k];
                        float4 pv;
                        pv.x = __shfl_xor_sync(0xffffffffu, val.x, srr);
                        pv.y = __shfl_xor_sync(0xffffffffu, val.y, srr);
                        pv.z = __shfl_xor_sync(0xffffffffu, val.z, srr);
                        pv.w = __shfl_xor_sync(0xffffffffu, val.w, srr);
                        v[j][k].x = w0v[j] * val.x + w1v[j] * pv.x;
                        v[j][k].y = w0v[j] * val.y + w1v[j] * pv.y;
                        v[j][k].z = w0v[j] * val.z + w1v[j] * pv.z;
                        v[j][k].w = w0v[j] * val.w + w1v[j] * pv.w;
                    }
            } else {
                const int dj = srr >> 5;     // 1 (stride 32) or 2 (stride 64)
                #pragma unroll
                for (int k = 0; k < 2; k++) {
                    const float4 ps[4] = {v[0][k], v[1][k], v[2][k], v[3][k]};
                    #pragma unroll
                    for (int j = 0; j < 4; j++) {
                        float4 a = ps[j], b = ps[j ^ dj];
                        v[j][k].x = w0v[j] * a.x + w1v[j] * b.x;
                        v[j][k].y = w0v[j] * a.y + w1v[j] * b.y;
                        v[j][k].z = w0v[j] * a.z + w1v[j] * b.z;
                        v[j][k].w = w0v[j] * a.w + w1v[j] * b.w;
                    }
                }
            }
        }

        // transpose scatter back (each element touched by exactly one thread)
        #pragma unroll
        for (int j = 0; j < 4; j++)
            #pragma unroll
            for (int k = 0; k < 2; k++)
                scr4[scf(lane + 32 * j, wid * 2 + k)] = v[j][k];
        __syncthreads();

        // coalesced global store
        #pragma unroll
        for (int rr = rw0; rr < 128; rr += 16) {
            int gr = grow_of(mode, blk, rr);
            ((float4*)out)[(size_t)gr * 32 + h * 16 + fc] = scr4[scf(rr, fc)];
        }
        __syncthreads();     // scr reused next half
    }
}

// ============================ launch ============================
extern "C" void kernel_launch(void* const* d_in, const int* in_sizes, int n_in,
                              void* d_out, int out_size) {
    const float* x = (const float*)d_in[0];   // (16, 8192, 128) f32
    const float* w = (const float*)d_in[1];   // (16, 2, 128, 128) f32
    float* out = (float*)d_out;

    const int smem_pre = (DIM * 129 + 4 * DIM) * 4;
    cudaFuncSetAttribute(precompute_M_kernel,
                         cudaFuncAttributeMaxDynamicSharedMemorySize, smem_pre);
    cudaFuncSetAttribute(butterfly_kernel,
                         cudaFuncAttributeMaxDynamicSharedMemorySize, SMEM_TOTAL);

    precompute_M_kernel<<<dim3(LOGN, 32), 512, smem_pre>>>(w);
    // stages 0..6 (strides 1..64): 128 contiguous rows per block
    butterfly_kernel<<<1024, THREADS, SMEM_TOTAL>>>(x, out, 7, 0, 0);
    // stages 7..12 (strides 128..4096): rows t0 + 64h + 128j per block
    butterfly_kernel<<<1024, THREADS, SMEM_TOTAL>>>(x, out, 6, 7, 1);
}